// round 2
// baseline (speedup 1.0000x reference)
#include <cuda_runtime.h>
#include <math.h>

#define NPLANETS      10
#define NEDGES_LOC    45
#define NT_PER_BLOCK  8
#define EDGES_PB      (NEDGES_LOC * NT_PER_BLOCK)   // 360
#define THREADS       384
#define HID           32

typedef unsigned long long ull;

__device__ __forceinline__ ull pk2(float x) {
    ull d; unsigned u = __float_as_uint(x);
    asm("mov.b64 %0, {%1, %1};" : "=l"(d) : "r"(u));
    return d;
}
__device__ __forceinline__ ull fma2(ull a, ull b, ull c) {
    ull d; asm("fma.rn.f32x2 %0, %1, %2, %3;" : "=l"(d) : "l"(a), "l"(b), "l"(c));
    return d;
}
__device__ __forceinline__ void upk(ull v, float& lo, float& hi) {
    unsigned a, b;
    asm("mov.b64 {%0, %1}, %2;" : "=r"(a), "=r"(b) : "l"(v));
    lo = __uint_as_float(a); hi = __uint_as_float(b);
}
__device__ __forceinline__ float tanha(float x) {
    float y; asm("tanh.approx.f32 %0, %1;" : "=f"(y) : "f"(x));
    return y;
}

__global__ void __launch_bounds__(THREADS)
learnforces_kernel(const float* __restrict__ D_V,
                   const float* __restrict__ logm,
                   const float* __restrict__ W1,
                   const float* __restrict__ b1,
                   const float* __restrict__ W2,
                   const float* __restrict__ b2,
                   const float* __restrict__ W3,
                   const float* __restrict__ b3,
                   const int*   __restrict__ senders,
                   const int*   __restrict__ receivers,
                   float*       __restrict__ out,
                   int ntime)
{
    __shared__ __align__(16) float sW1[3 * HID];     // feature rows r,theta,phi
    __shared__ __align__(16) float sW2[HID * HID];
    __shared__ __align__(16) float sW3[HID * 4];     // padded rows [w0,w1,w2,0]
    __shared__ __align__(16) float sb2[HID];
    __shared__ float sb3[4];
    __shared__ __align__(16) float sbias1[NEDGES_LOC * HID];
    __shared__ float s_lm[NPLANETS];
    __shared__ float s_invm[NPLANETS];
    __shared__ int   s_snd[NEDGES_LOC];
    __shared__ int   s_rcv[NEDGES_LOC];
    __shared__ int   s_glist[NPLANETS][9];           // +(le+1) recv, -(le+1) send
    __shared__ __align__(16) float4 s_e[EDGES_PB];   // per-edge cartesian force

    const int tid = threadIdx.x;

    // ---- cooperative setup ----
    for (int i = tid; i < 3 * HID; i += THREADS) sW1[i] = W1[i];
    for (int i = tid; i < HID * HID; i += THREADS) sW2[i] = W2[i];
    if (tid < HID) {
        sb2[tid] = b2[tid];
        sW3[tid * 4 + 0] = W3[tid * 3 + 0];
        sW3[tid * 4 + 1] = W3[tid * 3 + 1];
        sW3[tid * 4 + 2] = W3[tid * 3 + 2];
        sW3[tid * 4 + 3] = 0.0f;
    }
    if (tid < 4) sb3[tid] = (tid < 3) ? b3[tid] : 0.0f;
    if (tid < NEDGES_LOC) { s_snd[tid] = senders[tid]; s_rcv[tid] = receivers[tid]; }
    if (tid < NPLANETS) {
        float v = fminf(fmaxf(logm[tid], -12.0f), 12.0f);
        s_lm[tid]   = v;
        s_invm[tid] = expf(-v);
    }
    __syncthreads();

    // per-planet signed edge lists (gather-based scatter)
    if (tid < NPLANETS) {
        int cnt = 0;
        for (int le = 0; le < NEDGES_LOC; le++) {
            if (s_rcv[le] == tid) s_glist[tid][cnt++] =  (le + 1);
            else if (s_snd[le] == tid) s_glist[tid][cnt++] = -(le + 1);
        }
    }
    // bias1 table: b1 + lm[r]*W1row3 + lm[s]*W1row4
    for (int i = tid; i < NEDGES_LOC * HID; i += THREADS) {
        int le = i >> 5;
        int j  = i & 31;
        sbias1[i] = b1[j] + s_lm[s_rcv[le]] * W1[3 * HID + j]
                          + s_lm[s_snd[le]] * W1[4 * HID + j];
    }
    __syncthreads();

    // ---- per-edge compute ----
    const int  t_local = tid / NEDGES_LOC;
    const int  le      = tid - t_local * NEDGES_LOC;
    const long t_glob  = (long)blockIdx.x * NT_PER_BLOCK + t_local;

    if (tid < EDGES_PB && t_glob < (long)ntime) {
        long g = (long)blockIdx.x * EDGES_PB + tid;
        float x = D_V[g * 3 + 0];
        float y = D_V[g * 3 + 1];
        float z = D_V[g * 3 + 2];

        float r2 = fmaf(x, x, fmaf(y, y, z * z));
        float r  = sqrtf(r2);
        float ct = fminf(fmaxf(__fdividef(z, r), -1.0f), 1.0f);
        float th = acosf(ct);
        float ph = atan2f(y, x);

        // layer 1 (packed f32x2 over output-pairs) + tanh.approx
        float h1[HID];
        {
            ull rp  = pk2(r), tp = pk2(th), pp = pk2(ph);
            const ulonglong2* A0 = (const ulonglong2*)(sW1);
            const ulonglong2* A1 = (const ulonglong2*)(sW1 + HID);
            const ulonglong2* A2 = (const ulonglong2*)(sW1 + 2 * HID);
            const ulonglong2* BB = (const ulonglong2*)(sbias1 + le * HID);
#pragma unroll
            for (int q = 0; q < 8; q++) {
                ulonglong2 w0 = A0[q], w1 = A1[q], w2 = A2[q], bb = BB[q];
                ull t0 = fma2(rp, w0.x, fma2(tp, w1.x, fma2(pp, w2.x, bb.x)));
                ull t1 = fma2(rp, w0.y, fma2(tp, w1.y, fma2(pp, w2.y, bb.y)));
                float a, b;
                upk(t0, a, b); h1[4*q+0] = tanha(a); h1[4*q+1] = tanha(b);
                upk(t1, a, b); h1[4*q+2] = tanha(a); h1[4*q+3] = tanha(b);
            }
        }

        // layer 2: packed f32x2, k-outer over contiguous W2 rows
        ull acc[16];
        {
            const ulonglong2* bb = (const ulonglong2*)sb2;
#pragma unroll
            for (int q = 0; q < 8; q++) {
                ulonglong2 v = bb[q];
                acc[2*q] = v.x; acc[2*q+1] = v.y;
            }
#pragma unroll
            for (int k = 0; k < HID; k++) {
                ull hk = pk2(h1[k]);
                const ulonglong2* row = (const ulonglong2*)(sW2 + k * HID);
#pragma unroll
                for (int q = 0; q < 8; q++) {
                    ulonglong2 w = row[q];
                    acc[2*q]   = fma2(hk, w.x, acc[2*q]);
                    acc[2*q+1] = fma2(hk, w.y, acc[2*q+1]);
                }
            }
        }

        // layer 3: e = tanh(acc) @ W3 + b3
        float e0 = sb3[0], e1 = sb3[1], e2 = sb3[2];
        {
            const float4* w3 = (const float4*)sW3;
#pragma unroll
            for (int q = 0; q < 16; q++) {
                float lo, hi;
                upk(acc[q], lo, hi);
                float ha = tanha(lo), hb = tanha(hi);
                float4 wa = w3[2*q], wb = w3[2*q+1];
                e0 = fmaf(ha, wa.x, e0); e1 = fmaf(ha, wa.y, e1); e2 = fmaf(ha, wa.z, e2);
                e0 = fmaf(hb, wb.x, e0); e1 = fmaf(hb, wb.y, e1); e2 = fmaf(hb, wb.z, e2);
            }
        }

        // sph -> cart (fast sin/cos: args are tanh-bounded MLP outputs, small)
        float st, ctq, sp, cp;
        __sincosf(e1, &st, &ctq);
        __sincosf(e2, &sp, &cp);
        float rs = e0 * st;
        s_e[tid] = make_float4(rs * cp, rs * sp, e0 * ctq, 0.0f);
    }
    __syncthreads();

    // ---- gather-based scatter: 240 threads = 8 t * 10 planets * 3 comps ----
    if (tid < NT_PER_BLOCK * NPLANETS * 3) {
        int tl  = tid / (NPLANETS * 3);
        int rem = tid - tl * (NPLANETS * 3);
        int p   = rem / 3;
        int c   = rem - p * 3;
        long t  = (long)blockIdx.x * NT_PER_BLOCK + tl;
        if (t < (long)ntime) {
            const float* eb = (const float*)(s_e + tl * NEDGES_LOC);
            float sum = 0.0f;
#pragma unroll
            for (int k = 0; k < 9; k++) {
                int gidx = s_glist[p][k];
                int lle  = (gidx > 0 ? gidx : -gidx) - 1;
                float v  = eb[lle * 4 + c];
                sum += (gidx > 0) ? v : -v;
            }
            out[t * (NPLANETS * 3) + rem] = sum * s_invm[p];
        }
    }
}

extern "C" void kernel_launch(void* const* d_in, const int* in_sizes, int n_in,
                              void* d_out, int out_size)
{
    const float* D_V       = (const float*)d_in[0];
    const float* logm      = (const float*)d_in[1];
    const float* W1        = (const float*)d_in[2];
    const float* b1        = (const float*)d_in[3];
    const float* W2        = (const float*)d_in[4];
    const float* b2        = (const float*)d_in[5];
    const float* W3        = (const float*)d_in[6];
    const float* b3        = (const float*)d_in[7];
    const int*   senders   = (const int*)d_in[8];
    const int*   receivers = (const int*)d_in[9];
    float*       out       = (float*)d_out;

    int nedges = in_sizes[8];                  // 45
    int ntime  = in_sizes[0] / (3 * nedges);   // 100000

    int grid = (ntime + NT_PER_BLOCK - 1) / NT_PER_BLOCK;
    learnforces_kernel<<<grid, THREADS>>>(D_V, logm, W1, b1, W2, b2, W3, b3,
                                          senders, receivers, out, ntime);
}

// round 3
// speedup vs baseline: 1.5981x; 1.5981x over previous
#include <cuda_runtime.h>
#include <math.h>

#define NPLANETS      10
#define NEDGES_LOC    45
#define NT_PER_BLOCK  8
#define EDGES_PB      (NEDGES_LOC * NT_PER_BLOCK)   // 360
#define THREADS       384
#define HID           32
#define BSTRIDE       33                             // bank-conflict-free bias stride

__device__ __forceinline__ float tanha(float x) {
    float y; asm("tanh.approx.f32 %0, %1;" : "=f"(y) : "f"(x));
    return y;
}

__global__ void __launch_bounds__(THREADS, 2)
learnforces_kernel(const float* __restrict__ D_V,
                   const float* __restrict__ logm,
                   const float* __restrict__ W1,
                   const float* __restrict__ b1,
                   const float* __restrict__ W2,
                   const float* __restrict__ b2,
                   const float* __restrict__ W3,
                   const float* __restrict__ b3,
                   const int*   __restrict__ senders,
                   const int*   __restrict__ receivers,
                   float*       __restrict__ out,
                   int ntime)
{
    __shared__ __align__(16) float sW1[3 * HID];          // feature rows r,theta,phi
    __shared__ __align__(16) float sW2[HID * HID];
    __shared__ __align__(16) float sW3[HID * 4];          // padded rows [w0,w1,w2,0]
    __shared__ float sb3[4];
    __shared__ float sbias1[NEDGES_LOC * BSTRIDE];        // stride-33: conflict-free
    __shared__ float s_lm[NPLANETS];
    __shared__ float s_invm[NPLANETS];
    __shared__ int   s_snd[NEDGES_LOC];
    __shared__ int   s_rcv[NEDGES_LOC];
    __shared__ int   s_glist[NPLANETS][9];                // +(le+1) recv, -(le+1) send
    __shared__ __align__(16) float4 s_e[EDGES_PB];        // per-edge cartesian force

    const int tid = threadIdx.x;

    // ---- cooperative setup ----
    for (int i = tid; i < 3 * HID; i += THREADS) sW1[i] = W1[i];
    for (int i = tid; i < HID * HID; i += THREADS) sW2[i] = W2[i];
    if (tid < HID) {
        sW3[tid * 4 + 0] = W3[tid * 3 + 0];
        sW3[tid * 4 + 1] = W3[tid * 3 + 1];
        sW3[tid * 4 + 2] = W3[tid * 3 + 2];
        sW3[tid * 4 + 3] = 0.0f;
    }
    if (tid < 4) sb3[tid] = (tid < 3) ? b3[tid] : 0.0f;
    if (tid < NEDGES_LOC) { s_snd[tid] = senders[tid]; s_rcv[tid] = receivers[tid]; }
    if (tid < NPLANETS) {
        float v = fminf(fmaxf(logm[tid], -12.0f), 12.0f);
        s_lm[tid]   = v;
        s_invm[tid] = expf(-v);
    }
    __syncthreads();

    // per-planet signed edge lists (gather-based scatter)
    if (tid < NPLANETS) {
        int cnt = 0;
        for (int le = 0; le < NEDGES_LOC; le++) {
            if (s_rcv[le] == tid) s_glist[tid][cnt++] =  (le + 1);
            else if (s_snd[le] == tid) s_glist[tid][cnt++] = -(le + 1);
        }
    }
    // bias1 table: b1 + lm[r]*W1row3 + lm[s]*W1row4  (stored at stride 33)
    for (int i = tid; i < NEDGES_LOC * HID; i += THREADS) {
        int le = i >> 5;
        int j  = i & 31;
        sbias1[le * BSTRIDE + j] = b1[j] + s_lm[s_rcv[le]] * W1[3 * HID + j]
                                         + s_lm[s_snd[le]] * W1[4 * HID + j];
    }
    __syncthreads();

    // ---- per-edge compute ----
    const int  t_local = tid / NEDGES_LOC;
    const int  le      = tid - t_local * NEDGES_LOC;
    const long t_glob  = (long)blockIdx.x * NT_PER_BLOCK + t_local;

    if (tid < EDGES_PB && t_glob < (long)ntime) {
        long g = (long)blockIdx.x * EDGES_PB + tid;
        float x = D_V[g * 3 + 0];
        float y = D_V[g * 3 + 1];
        float z = D_V[g * 3 + 2];

        float r2 = fmaf(x, x, fmaf(y, y, z * z));
        float r  = sqrtf(r2);
        float ct = fminf(fmaxf(__fdividef(z, r), -1.0f), 1.0f);
        float th = acosf(ct);
        float ph = atan2f(y, x);

        const float* bias = sbias1 + le * BSTRIDE;

        // fused layer1+layer2: rank-1 update of acc[32] per k (no h1 array)
        float acc[HID];
#pragma unroll
        for (int q = 0; q < HID; q++) acc[q] = b2[q];     // b2 via read-only cache (broadcast)

#pragma unroll 4
        for (int k = 0; k < HID; k++) {
            float pre = fmaf(r,  sW1[k],
                        fmaf(th, sW1[HID + k],
                        fmaf(ph, sW1[2 * HID + k], bias[k])));
            float hk = tanha(pre);
            const float4* row = (const float4*)(sW2 + k * HID);
#pragma unroll
            for (int q = 0; q < 8; q++) {
                float4 w = row[q];
                acc[4*q+0] = fmaf(hk, w.x, acc[4*q+0]);
                acc[4*q+1] = fmaf(hk, w.y, acc[4*q+1]);
                acc[4*q+2] = fmaf(hk, w.z, acc[4*q+2]);
                acc[4*q+3] = fmaf(hk, w.w, acc[4*q+3]);
            }
        }

        // layer 3: e = tanh(acc) @ W3 + b3
        float e0 = sb3[0], e1 = sb3[1], e2 = sb3[2];
        {
            const float4* w3 = (const float4*)sW3;
#pragma unroll
            for (int k = 0; k < HID; k++) {
                float hk = tanha(acc[k]);
                float4 w = w3[k];
                e0 = fmaf(hk, w.x, e0);
                e1 = fmaf(hk, w.y, e1);
                e2 = fmaf(hk, w.z, e2);
            }
        }

        // sph -> cart
        float st, ctq, sp, cp;
        __sincosf(e1, &st, &ctq);
        __sincosf(e2, &sp, &cp);
        float rs = e0 * st;
        s_e[tid] = make_float4(rs * cp, rs * sp, e0 * ctq, 0.0f);
    }
    __syncthreads();

    // ---- gather-based scatter: 240 threads = 8 t * 10 planets * 3 comps ----
    if (tid < NT_PER_BLOCK * NPLANETS * 3) {
        int tl  = tid / (NPLANETS * 3);
        int rem = tid - tl * (NPLANETS * 3);
        int p   = rem / 3;
        int c   = rem - p * 3;
        long t  = (long)blockIdx.x * NT_PER_BLOCK + tl;
        if (t < (long)ntime) {
            const float* eb = (const float*)(s_e + tl * NEDGES_LOC);
            float sum = 0.0f;
#pragma unroll
            for (int k = 0; k < 9; k++) {
                int gidx = s_glist[p][k];
                int lle  = (gidx > 0 ? gidx : -gidx) - 1;
                float v  = eb[lle * 4 + c];
                sum += (gidx > 0) ? v : -v;
            }
            out[t * (NPLANETS * 3) + rem] = sum * s_invm[p];
        }
    }
}

extern "C" void kernel_launch(void* const* d_in, const int* in_sizes, int n_in,
                              void* d_out, int out_size)
{
    const float* D_V       = (const float*)d_in[0];
    const float* logm      = (const float*)d_in[1];
    const float* W1        = (const float*)d_in[2];
    const float* b1        = (const float*)d_in[3];
    const float* W2        = (const float*)d_in[4];
    const float* b2        = (const float*)d_in[5];
    const float* W3        = (const float*)d_in[6];
    const float* b3        = (const float*)d_in[7];
    const int*   senders   = (const int*)d_in[8];
    const int*   receivers = (const int*)d_in[9];
    float*       out       = (float*)d_out;

    int nedges = in_sizes[8];                  // 45
    int ntime  = in_sizes[0] / (3 * nedges);   // 100000

    int grid = (ntime + NT_PER_BLOCK - 1) / NT_PER_BLOCK;
    learnforces_kernel<<<grid, THREADS>>>(D_V, logm, W1, b1, W2, b2, W3, b3,
                                          senders, receivers, out, ntime);
}

// round 4
// speedup vs baseline: 2.2963x; 1.4368x over previous
#include <cuda_runtime.h>
#include <math.h>

#define NPLANETS      10
#define NEDGES_LOC    45
#define NT_PER_BLOCK  8
#define EDGES_PB      (NEDGES_LOC * NT_PER_BLOCK)   // 360
#define THREADS       384
#define HID           32
#define BSTRIDE       33

// Weights in constant memory: all hot-loop accesses are warp-uniform ->
// LDCU on the uniform-constant port (separate from L1tex/smem crossbar).
__constant__ float cW1[5 * HID];
__constant__ float cW2[HID * HID];
__constant__ float cW3[HID * 3];
__constant__ float cb2[HID];
__constant__ float cb3[3];

__device__ __forceinline__ float tanha(float x) {
    float y; asm("tanh.approx.f32 %0, %1;" : "=f"(y) : "f"(x));
    return y;
}

__global__ void __launch_bounds__(THREADS, 2)
learnforces_kernel(const float* __restrict__ D_V,
                   const float* __restrict__ logm,
                   const float* __restrict__ W1,
                   const float* __restrict__ b1,
                   const int*   __restrict__ senders,
                   const int*   __restrict__ receivers,
                   float*       __restrict__ out,
                   int ntime)
{
    __shared__ float sbias1[NEDGES_LOC * BSTRIDE];        // stride-33: conflict-free
    __shared__ float s_lm[NPLANETS];
    __shared__ float s_invm[NPLANETS];
    __shared__ int   s_snd[NEDGES_LOC];
    __shared__ int   s_rcv[NEDGES_LOC];
    __shared__ int   s_glist[NPLANETS][9];                // +(le+1) recv, -(le+1) send
    __shared__ __align__(16) float4 s_e[EDGES_PB];        // per-edge cartesian force

    const int tid = threadIdx.x;

    // ---- cooperative setup (divergent weight reads stay on global/L1) ----
    if (tid < NEDGES_LOC) { s_snd[tid] = senders[tid]; s_rcv[tid] = receivers[tid]; }
    if (tid < NPLANETS) {
        float v = fminf(fmaxf(logm[tid], -12.0f), 12.0f);
        s_lm[tid]   = v;
        s_invm[tid] = expf(-v);
    }
    __syncthreads();

    if (tid < NPLANETS) {
        int cnt = 0;
        for (int le = 0; le < NEDGES_LOC; le++) {
            if (s_rcv[le] == tid) s_glist[tid][cnt++] =  (le + 1);
            else if (s_snd[le] == tid) s_glist[tid][cnt++] = -(le + 1);
        }
    }
    // bias1 table: b1 + lm[r]*W1row3 + lm[s]*W1row4  (global reads, one-off)
    for (int i = tid; i < NEDGES_LOC * HID; i += THREADS) {
        int le = i >> 5;
        int j  = i & 31;
        sbias1[le * BSTRIDE + j] = b1[j] + s_lm[s_rcv[le]] * W1[3 * HID + j]
                                         + s_lm[s_snd[le]] * W1[4 * HID + j];
    }
    __syncthreads();

    // ---- per-edge compute ----
    const int  t_local = tid / NEDGES_LOC;
    const int  le      = tid - t_local * NEDGES_LOC;
    const long t_glob  = (long)blockIdx.x * NT_PER_BLOCK + t_local;

    if (tid < EDGES_PB && t_glob < (long)ntime) {
        long g = (long)blockIdx.x * EDGES_PB + tid;
        float x = D_V[g * 3 + 0];
        float y = D_V[g * 3 + 1];
        float z = D_V[g * 3 + 2];

        float r2 = fmaf(x, x, fmaf(y, y, z * z));
        float r  = sqrtf(r2);
        float ct = fminf(fmaxf(__fdividef(z, r), -1.0f), 1.0f);
        float th = acosf(ct);
        float ph = atan2f(y, x);

        const float* bias = sbias1 + le * BSTRIDE;

        // fused layer1+layer2: rank-1 update of acc[32] per k.
        // All cW1/cW2 indices are warp-uniform -> LDCU + UR-operand FFMA.
        float acc[HID];
#pragma unroll
        for (int q = 0; q < HID; q++) acc[q] = cb2[q];

#pragma unroll 4
        for (int k = 0; k < HID; k++) {
            float pre = fmaf(r,  cW1[k],
                        fmaf(th, cW1[HID + k],
                        fmaf(ph, cW1[2 * HID + k], bias[k])));
            float hk = tanha(pre);
            const float* row = cW2 + k * HID;
#pragma unroll
            for (int q = 0; q < HID; q++)
                acc[q] = fmaf(hk, row[q], acc[q]);
        }

        // layer 3: e = tanh(acc) @ W3 + b3  (uniform cW3 reads)
        float e0 = cb3[0], e1 = cb3[1], e2 = cb3[2];
#pragma unroll
        for (int k = 0; k < HID; k++) {
            float hk = tanha(acc[k]);
            e0 = fmaf(hk, cW3[k * 3 + 0], e0);
            e1 = fmaf(hk, cW3[k * 3 + 1], e1);
            e2 = fmaf(hk, cW3[k * 3 + 2], e2);
        }

        // sph -> cart
        float st, ctq, sp, cp;
        __sincosf(e1, &st, &ctq);
        __sincosf(e2, &sp, &cp);
        float rs = e0 * st;
        s_e[tid] = make_float4(rs * cp, rs * sp, e0 * ctq, 0.0f);
    }
    __syncthreads();

    // ---- gather-based scatter: 240 threads = 8 t * 10 planets * 3 comps ----
    if (tid < NT_PER_BLOCK * NPLANETS * 3) {
        int tl  = tid / (NPLANETS * 3);
        int rem = tid - tl * (NPLANETS * 3);
        int p   = rem / 3;
        int c   = rem - p * 3;
        long t  = (long)blockIdx.x * NT_PER_BLOCK + tl;
        if (t < (long)ntime) {
            const float* eb = (const float*)(s_e + tl * NEDGES_LOC);
            float sum = 0.0f;
#pragma unroll
            for (int k = 0; k < 9; k++) {
                int gidx = s_glist[p][k];
                int lle  = (gidx > 0 ? gidx : -gidx) - 1;
                float v  = eb[lle * 4 + c];
                sum += (gidx > 0) ? v : -v;
            }
            out[t * (NPLANETS * 3) + rem] = sum * s_invm[p];
        }
    }
}

extern "C" void kernel_launch(void* const* d_in, const int* in_sizes, int n_in,
                              void* d_out, int out_size)
{
    const float* D_V       = (const float*)d_in[0];
    const float* logm      = (const float*)d_in[1];
    const float* W1        = (const float*)d_in[2];
    const float* b1        = (const float*)d_in[3];
    const float* W2        = (const float*)d_in[4];
    const float* b2        = (const float*)d_in[5];
    const float* W3        = (const float*)d_in[6];
    const float* b3        = (const float*)d_in[7];
    const int*   senders   = (const int*)d_in[8];
    const int*   receivers = (const int*)d_in[9];
    float*       out       = (float*)d_out;

    // Stage weights into __constant__ (D2D async copies: graph-capturable,
    // no allocation; replayed deterministically with the graph).
    cudaMemcpyToSymbolAsync(cW1, W1, 5 * HID * sizeof(float), 0, cudaMemcpyDeviceToDevice);
    cudaMemcpyToSymbolAsync(cW2, W2, HID * HID * sizeof(float), 0, cudaMemcpyDeviceToDevice);
    cudaMemcpyToSymbolAsync(cW3, W3, HID * 3 * sizeof(float), 0, cudaMemcpyDeviceToDevice);
    cudaMemcpyToSymbolAsync(cb2, b2, HID * sizeof(float), 0, cudaMemcpyDeviceToDevice);
    cudaMemcpyToSymbolAsync(cb3, b3, 3 * sizeof(float), 0, cudaMemcpyDeviceToDevice);

    int nedges = in_sizes[8];                  // 45
    int ntime  = in_sizes[0] / (3 * nedges);   // 100000

    int grid = (ntime + NT_PER_BLOCK - 1) / NT_PER_BLOCK;
    learnforces_kernel<<<grid, THREADS>>>(D_V, logm, W1, b1,
                                          senders, receivers, out, ntime);
}

// round 5
// speedup vs baseline: 2.5874x; 1.1268x over previous
#include <cuda_runtime.h>
#include <math.h>

#define NPLANETS      10
#define NEDGES_LOC    45
#define NT_PER_BLOCK  8
#define EDGES_PB      (NEDGES_LOC * NT_PER_BLOCK)   // 360
#define THREADS       384
#define HID           32
#define BSTRIDE       33

typedef unsigned long long ull;

// Weights in constant memory. W2/b2 stored as pre-packed 64-bit float pairs
// (ulonglong2 = 4 floats): LDCU.128 yields ready-to-use fma.rn.f32x2 operands
// with zero pack instructions.
__constant__ float      cW1[3 * HID];
__constant__ ulonglong2 cW2p[HID * HID / 4];   // 256 x (4 floats)
__constant__ ulonglong2 cb2p[HID / 4];
__constant__ float      cW3[HID * 3];
__constant__ float      cb3[3];

__device__ __forceinline__ float tanha(float x) {
    float y; asm("tanh.approx.f32 %0, %1;" : "=f"(y) : "f"(x));
    return y;
}
__device__ __forceinline__ ull pk2(float x) {
    ull d; unsigned u = __float_as_uint(x);
    asm("mov.b64 %0, {%1, %1};" : "=l"(d) : "r"(u));
    return d;
}
__device__ __forceinline__ ull fma2(ull a, ull b, ull c) {
    ull d; asm("fma.rn.f32x2 %0, %1, %2, %3;" : "=l"(d) : "l"(a), "l"(b), "l"(c));
    return d;
}
__device__ __forceinline__ void upk(ull v, float& lo, float& hi) {
    unsigned a, b;
    asm("mov.b64 {%0, %1}, %2;" : "=r"(a), "=r"(b) : "l"(v));
    lo = __uint_as_float(a); hi = __uint_as_float(b);
}

__global__ void __launch_bounds__(THREADS, 2)
learnforces_kernel(const float* __restrict__ D_V,
                   const float* __restrict__ logm,
                   const float* __restrict__ W1,
                   const float* __restrict__ b1,
                   const int*   __restrict__ senders,
                   const int*   __restrict__ receivers,
                   float*       __restrict__ out,
                   int ntime)
{
    __shared__ float sbias1[NEDGES_LOC * BSTRIDE];        // stride-33: conflict-free
    __shared__ float s_lm[NPLANETS];
    __shared__ float s_invm[NPLANETS];
    __shared__ int   s_snd[NEDGES_LOC];
    __shared__ int   s_rcv[NEDGES_LOC];
    __shared__ int   s_glist[NPLANETS][9];                // +(le+1) recv, -(le+1) send
    __shared__ __align__(16) float4 s_e[EDGES_PB];        // per-edge cartesian force

    const int tid = threadIdx.x;

    // ---- cooperative setup ----
    if (tid < NEDGES_LOC) { s_snd[tid] = senders[tid]; s_rcv[tid] = receivers[tid]; }
    if (tid < NPLANETS) {
        float v = fminf(fmaxf(logm[tid], -12.0f), 12.0f);
        s_lm[tid]   = v;
        s_invm[tid] = expf(-v);
    }
    __syncthreads();

    if (tid < NPLANETS) {
        int cnt = 0;
        for (int le = 0; le < NEDGES_LOC; le++) {
            if (s_rcv[le] == tid) s_glist[tid][cnt++] =  (le + 1);
            else if (s_snd[le] == tid) s_glist[tid][cnt++] = -(le + 1);
        }
    }
    // bias1 table: b1 + lm[r]*W1row3 + lm[s]*W1row4  (global reads, one-off)
    for (int i = tid; i < NEDGES_LOC * HID; i += THREADS) {
        int le = i >> 5;
        int j  = i & 31;
        sbias1[le * BSTRIDE + j] = b1[j] + s_lm[s_rcv[le]] * W1[3 * HID + j]
                                         + s_lm[s_snd[le]] * W1[4 * HID + j];
    }
    __syncthreads();

    // ---- per-edge compute ----
    const int  t_local = tid / NEDGES_LOC;
    const int  le      = tid - t_local * NEDGES_LOC;
    const long t_glob  = (long)blockIdx.x * NT_PER_BLOCK + t_local;

    if (tid < EDGES_PB && t_glob < (long)ntime) {
        long g = (long)blockIdx.x * EDGES_PB + tid;
        float x = D_V[g * 3 + 0];
        float y = D_V[g * 3 + 1];
        float z = D_V[g * 3 + 2];

        float r2 = fmaf(x, x, fmaf(y, y, z * z));
        float r  = sqrtf(r2);
        float ct = fminf(fmaxf(__fdividef(z, r), -1.0f), 1.0f);
        float th = acosf(ct);
        float ph = atan2f(y, x);

        const float* bias = sbias1 + le * BSTRIDE;

        // fused layer1+layer2: scalar layer-1 activation, packed f32x2
        // rank-1 update of acc (16 x 64-bit pairs covering 32 outputs).
        ull acc[16];
#pragma unroll
        for (int q = 0; q < 8; q++) {
            ulonglong2 v = cb2p[q];
            acc[2*q] = v.x; acc[2*q+1] = v.y;
        }

#pragma unroll 4
        for (int k = 0; k < HID; k++) {
            float pre = fmaf(r,  cW1[k],
                        fmaf(th, cW1[HID + k],
                        fmaf(ph, cW1[2 * HID + k], bias[k])));
            ull hk = pk2(tanha(pre));
#pragma unroll
            for (int q = 0; q < 8; q++) {
                ulonglong2 w = cW2p[k * 8 + q];
                acc[2*q]   = fma2(hk, w.x, acc[2*q]);
                acc[2*q+1] = fma2(hk, w.y, acc[2*q+1]);
            }
        }

        // layer 3: e = tanh(acc) @ W3 + b3
        float e0 = cb3[0], e1 = cb3[1], e2 = cb3[2];
#pragma unroll
        for (int q = 0; q < 16; q++) {
            float lo, hi;
            upk(acc[q], lo, hi);
            float ha = tanha(lo), hb = tanha(hi);
            int k = 2 * q;
            e0 = fmaf(ha, cW3[k * 3 + 0], e0);
            e1 = fmaf(ha, cW3[k * 3 + 1], e1);
            e2 = fmaf(ha, cW3[k * 3 + 2], e2);
            e0 = fmaf(hb, cW3[k * 3 + 3], e0);
            e1 = fmaf(hb, cW3[k * 3 + 4], e1);
            e2 = fmaf(hb, cW3[k * 3 + 5], e2);
        }

        // sph -> cart
        float st, ctq, sp, cp;
        __sincosf(e1, &st, &ctq);
        __sincosf(e2, &sp, &cp);
        float rs = e0 * st;
        s_e[tid] = make_float4(rs * cp, rs * sp, e0 * ctq, 0.0f);
    }
    __syncthreads();

    // ---- gather-based scatter: 240 threads = 8 t * 10 planets * 3 comps ----
    if (tid < NT_PER_BLOCK * NPLANETS * 3) {
        int tl  = tid / (NPLANETS * 3);
        int rem = tid - tl * (NPLANETS * 3);
        int p   = rem / 3;
        int c   = rem - p * 3;
        long t  = (long)blockIdx.x * NT_PER_BLOCK + tl;
        if (t < (long)ntime) {
            const float* eb = (const float*)(s_e + tl * NEDGES_LOC);
            float sum = 0.0f;
#pragma unroll
            for (int k = 0; k < 9; k++) {
                int gidx = s_glist[p][k];
                int lle  = (gidx > 0 ? gidx : -gidx) - 1;
                float v  = eb[lle * 4 + c];
                sum += (gidx > 0) ? v : -v;
            }
            out[t * (NPLANETS * 3) + rem] = sum * s_invm[p];
        }
    }
}

extern "C" void kernel_launch(void* const* d_in, const int* in_sizes, int n_in,
                              void* d_out, int out_size)
{
    const float* D_V       = (const float*)d_in[0];
    const float* logm      = (const float*)d_in[1];
    const float* W1        = (const float*)d_in[2];
    const float* b1        = (const float*)d_in[3];
    const float* W2        = (const float*)d_in[4];
    const float* b2        = (const float*)d_in[5];
    const float* W3        = (const float*)d_in[6];
    const float* b3        = (const float*)d_in[7];
    const int*   senders   = (const int*)d_in[8];
    const int*   receivers = (const int*)d_in[9];
    float*       out       = (float*)d_out;

    // Stage weights into __constant__ (graph-capturable async D2D copies).
    cudaMemcpyToSymbolAsync(cW1,  W1, 3 * HID * sizeof(float), 0, cudaMemcpyDeviceToDevice);
    cudaMemcpyToSymbolAsync(cW2p, W2, HID * HID * sizeof(float), 0, cudaMemcpyDeviceToDevice);
    cudaMemcpyToSymbolAsync(cb2p, b2, HID * sizeof(float), 0, cudaMemcpyDeviceToDevice);
    cudaMemcpyToSymbolAsync(cW3,  W3, HID * 3 * sizeof(float), 0, cudaMemcpyDeviceToDevice);
    cudaMemcpyToSymbolAsync(cb3,  b3, 3 * sizeof(float), 0, cudaMemcpyDeviceToDevice);

    int nedges = in_sizes[8];                  // 45
    int ntime  = in_sizes[0] / (3 * nedges);   // 100000

    int grid = (ntime + NT_PER_BLOCK - 1) / NT_PER_BLOCK;
    learnforces_kernel<<<grid, THREADS>>>(D_V, logm, W1, b1,
                                          senders, receivers, out, ntime);
}

// round 6
// speedup vs baseline: 3.2986x; 1.2749x over previous
#include <cuda_runtime.h>
#include <math.h>

#define NPLANETS      10
#define NEDGES_LOC    45
#define NT_PER_BLOCK  8
#define EDGES_PB      (NEDGES_LOC * NT_PER_BLOCK)   // 360
#define THREADS       384
#define HID           32
#define BSTRIDE       33

typedef unsigned long long ull;

// Weights in constant memory. W2/b2 stored as pre-packed 64-bit float pairs
// (ulonglong2 = 4 floats): LDCU.128 yields ready-to-use fma.rn.f32x2 operands
// with zero pack instructions.
__constant__ float      cW1[3 * HID];
__constant__ ulonglong2 cW2p[HID * HID / 4];   // 256 x (4 floats)
__constant__ ulonglong2 cb2p[HID / 4];
__constant__ float      cW3[HID * 3];
__constant__ float      cb3[3];

__device__ __forceinline__ float tanha(float x) {
    float y; asm("tanh.approx.f32 %0, %1;" : "=f"(y) : "f"(x));
    return y;
}
__device__ __forceinline__ ull pk2(float x) {
    ull d; unsigned u = __float_as_uint(x);
    asm("mov.b64 %0, {%1, %1};" : "=l"(d) : "r"(u));
    return d;
}
__device__ __forceinline__ ull fma2(ull a, ull b, ull c) {
    ull d; asm("fma.rn.f32x2 %0, %1, %2, %3;" : "=l"(d) : "l"(a), "l"(b), "l"(c));
    return d;
}
__device__ __forceinline__ void upk(ull v, float& lo, float& hi) {
    unsigned a, b;
    asm("mov.b64 {%0, %1}, %2;" : "=r"(a), "=r"(b) : "l"(v));
    lo = __uint_as_float(a); hi = __uint_as_float(b);
}

__global__ void __launch_bounds__(THREADS, 3)
learnforces_kernel(const float* __restrict__ D_V,
                   const float* __restrict__ logm,
                   const float* __restrict__ W1,
                   const float* __restrict__ b1,
                   const int*   __restrict__ senders,
                   const int*   __restrict__ receivers,
                   float*       __restrict__ out,
                   int ntime)
{
    __shared__ float sbias1[NEDGES_LOC * BSTRIDE];        // stride-33: conflict-free
    __shared__ float s_lm[NPLANETS];
    __shared__ float s_invm[NPLANETS];
    __shared__ int   s_snd[NEDGES_LOC];
    __shared__ int   s_rcv[NEDGES_LOC];
    __shared__ int   s_glist[NPLANETS][9];                // +(le+1) recv, -(le+1) send
    __shared__ __align__(16) float4 s_e[EDGES_PB];        // per-edge cartesian force

    const int tid = threadIdx.x;

    // ---- cooperative setup ----
    if (tid < NEDGES_LOC) { s_snd[tid] = senders[tid]; s_rcv[tid] = receivers[tid]; }
    if (tid < NPLANETS) {
        float v = fminf(fmaxf(logm[tid], -12.0f), 12.0f);
        s_lm[tid]   = v;
        s_invm[tid] = expf(-v);
    }
    __syncthreads();

    if (tid < NPLANETS) {
        int cnt = 0;
        for (int le = 0; le < NEDGES_LOC; le++) {
            if (s_rcv[le] == tid) s_glist[tid][cnt++] =  (le + 1);
            else if (s_snd[le] == tid) s_glist[tid][cnt++] = -(le + 1);
        }
    }
    // bias1 table: b1 + lm[r]*W1row3 + lm[s]*W1row4  (global reads, one-off)
    for (int i = tid; i < NEDGES_LOC * HID; i += THREADS) {
        int le = i >> 5;
        int j  = i & 31;
        sbias1[le * BSTRIDE + j] = b1[j] + s_lm[s_rcv[le]] * W1[3 * HID + j]
                                         + s_lm[s_snd[le]] * W1[4 * HID + j];
    }
    __syncthreads();

    // ---- per-edge compute ----
    const int  t_local = tid / NEDGES_LOC;
    const int  le      = tid - t_local * NEDGES_LOC;
    const long t_glob  = (long)blockIdx.x * NT_PER_BLOCK + t_local;

    if (tid < EDGES_PB && t_glob < (long)ntime) {
        long g = (long)blockIdx.x * EDGES_PB + tid;
        float x = D_V[g * 3 + 0];
        float y = D_V[g * 3 + 1];
        float z = D_V[g * 3 + 2];

        float r2 = fmaf(x, x, fmaf(y, y, z * z));
        float r  = sqrtf(r2);
        float ct = fminf(fmaxf(__fdividef(z, r), -1.0f), 1.0f);
        float th = acosf(ct);
        float ph = atan2f(y, x);

        const float* bias = sbias1 + le * BSTRIDE;

        // fused layer1+layer2: scalar layer-1 activation, packed f32x2
        // rank-1 update of acc (16 x 64-bit pairs covering 32 outputs).
        ull acc[16];
#pragma unroll
        for (int q = 0; q < 8; q++) {
            ulonglong2 v = cb2p[q];
            acc[2*q] = v.x; acc[2*q+1] = v.y;
        }

#pragma unroll
        for (int k = 0; k < HID; k++) {
            float pre = fmaf(r,  cW1[k],
                        fmaf(th, cW1[HID + k],
                        fmaf(ph, cW1[2 * HID + k], bias[k])));
            ull hk = pk2(tanha(pre));
#pragma unroll
            for (int q = 0; q < 8; q++) {
                ulonglong2 w = cW2p[k * 8 + q];
                acc[2*q]   = fma2(hk, w.x, acc[2*q]);
                acc[2*q+1] = fma2(hk, w.y, acc[2*q+1]);
            }
        }

        // layer 3: e = tanh(acc) @ W3 + b3
        float e0 = cb3[0], e1 = cb3[1], e2 = cb3[2];
#pragma unroll
        for (int q = 0; q < 16; q++) {
            float lo, hi;
            upk(acc[q], lo, hi);
            float ha = tanha(lo), hb = tanha(hi);
            int k = 2 * q;
            e0 = fmaf(ha, cW3[k * 3 + 0], e0);
            e1 = fmaf(ha, cW3[k * 3 + 1], e1);
            e2 = fmaf(ha, cW3[k * 3 + 2], e2);
            e0 = fmaf(hb, cW3[k * 3 + 3], e0);
            e1 = fmaf(hb, cW3[k * 3 + 4], e1);
            e2 = fmaf(hb, cW3[k * 3 + 5], e2);
        }

        // sph -> cart
        float st, ctq, sp, cp;
        __sincosf(e1, &st, &ctq);
        __sincosf(e2, &sp, &cp);
        float rs = e0 * st;
        s_e[tid] = make_float4(rs * cp, rs * sp, e0 * ctq, 0.0f);
    }
    __syncthreads();

    // ---- gather-based scatter: 240 threads = 8 t * 10 planets * 3 comps ----
    if (tid < NT_PER_BLOCK * NPLANETS * 3) {
        int tl  = tid / (NPLANETS * 3);
        int rem = tid - tl * (NPLANETS * 3);
        int p   = rem / 3;
        int c   = rem - p * 3;
        long t  = (long)blockIdx.x * NT_PER_BLOCK + tl;
        if (t < (long)ntime) {
            const float* eb = (const float*)(s_e + tl * NEDGES_LOC);
            float sum = 0.0f;
#pragma unroll
            for (int k = 0; k < 9; k++) {
                int gidx = s_glist[p][k];
                int lle  = (gidx > 0 ? gidx : -gidx) - 1;
                float v  = eb[lle * 4 + c];
                sum += (gidx > 0) ? v : -v;
            }
            out[t * (NPLANETS * 3) + rem] = sum * s_invm[p];
        }
    }
}

extern "C" void kernel_launch(void* const* d_in, const int* in_sizes, int n_in,
                              void* d_out, int out_size)
{
    const float* D_V       = (const float*)d_in[0];
    const float* logm      = (const float*)d_in[1];
    const float* W1        = (const float*)d_in[2];
    const float* b1        = (const float*)d_in[3];
    const float* W2        = (const float*)d_in[4];
    const float* b2        = (const float*)d_in[5];
    const float* W3        = (const float*)d_in[6];
    const float* b3        = (const float*)d_in[7];
    const int*   senders   = (const int*)d_in[8];
    const int*   receivers = (const int*)d_in[9];
    float*       out       = (float*)d_out;

    // Stage weights into __constant__ (graph-capturable async D2D copies).
    cudaMemcpyToSymbolAsync(cW1,  W1, 3 * HID * sizeof(float), 0, cudaMemcpyDeviceToDevice);
    cudaMemcpyToSymbolAsync(cW2p, W2, HID * HID * sizeof(float), 0, cudaMemcpyDeviceToDevice);
    cudaMemcpyToSymbolAsync(cb2p, b2, HID * sizeof(float), 0, cudaMemcpyDeviceToDevice);
    cudaMemcpyToSymbolAsync(cW3,  W3, HID * 3 * sizeof(float), 0, cudaMemcpyDeviceToDevice);
    cudaMemcpyToSymbolAsync(cb3,  b3, 3 * sizeof(float), 0, cudaMemcpyDeviceToDevice);

    int nedges = in_sizes[8];                  // 45
    int ntime  = in_sizes[0] / (3 * nedges);   // 100000

    int grid = (ntime + NT_PER_BLOCK - 1) / NT_PER_BLOCK;
    learnforces_kernel<<<grid, THREADS>>>(D_V, logm, W1, b1,
                                          senders, receivers, out, ntime);
}